// round 3
// baseline (speedup 1.0000x reference)
#include <cuda_runtime.h>
#include <cstdint>

// Problem dims (fixed by the reference)
#define BB   16
#define TT   512
#define HH   512
#define BT   (BB*TT)        // 8192
#define NH   8
#define DH   64             // head dim
#define NBH  (BB*NH)        // 128 batched attention mats

typedef unsigned long long ull;

// ---------------------------------------------------------------------------
// Scratch (static device globals — no allocation)
// ---------------------------------------------------------------------------
__device__ float g_Q [(size_t)BT*HH];
__device__ float g_K [(size_t)BT*HH];
__device__ float g_V [(size_t)BT*HH];
__device__ float g_O [(size_t)BT*HH];
__device__ float g_X [(size_t)BT*HH];
__device__ float g_WX[(size_t)BT*HH];
__device__ float g_S [(size_t)NBH*TT*TT];     // 134 MB attention scores
__device__ float g_psum[(size_t)256*HH];
__device__ float g_psq [(size_t)256*HH];
__device__ float g_sum [HH];
__device__ float g_sq  [HH];

// ---------------------------------------------------------------------------
// f32x2 packed math (sm_103a FFMA2 — PTX-only)
// ---------------------------------------------------------------------------
__device__ __forceinline__ ull ffma2(ull a, ull b, ull c) {
    ull d; asm("fma.rn.f32x2 %0, %1, %2, %3;" : "=l"(d) : "l"(a), "l"(b), "l"(c));
    return d;
}
__device__ __forceinline__ void unpack2(ull v, float& x, float& y) {
    asm("mov.b64 {%0, %1}, %2;" : "=f"(x), "=f"(y) : "l"(v));
}

// ---------------------------------------------------------------------------
// Accurate expf, immune to --use_fast_math.
// ---------------------------------------------------------------------------
__device__ __forceinline__ float exp_acc(float x) {
    x = fmaxf(x, -87.0f);
    float z = x * 1.44269504088896341f;
    float n = rintf(z);
    float f = fmaf(n, -0.693145751953125f, x);
    f = fmaf(n, -1.428606765330187e-06f, f);
    float p = 1.9841269841e-4f;
    p = fmaf(p, f, 1.3888888889e-3f);
    p = fmaf(p, f, 8.3333333333e-3f);
    p = fmaf(p, f, 4.1666666667e-2f);
    p = fmaf(p, f, 1.6666666667e-1f);
    p = fmaf(p, f, 0.5f);
    p = fmaf(p, f, 1.0f);
    p = fmaf(p, f, 1.0f);
    int ni = (int)n;
    float sc = __int_as_float((ni + 127) << 23);
    return p * sc;
}

// ---------------------------------------------------------------------------
// fp32 GEMM, f32x2 accumulation, duplicated-A smem (no packing MOVs in the
// inner loop), double-buffered smem (one barrier per K-tile).
//   BM=128, BK=16, 256 threads, TM=8, TN(8|4).
// ---------------------------------------------------------------------------
template<int BN, int TN, bool TRANSB, bool RESID>
__global__ __launch_bounds__(256, 2)
void gemm3(const float* __restrict__ A, const float* __restrict__ Bm,
           float* __restrict__ C, const float* __restrict__ R,
           int M, int N, int K, int lda, int ldb, int ldc, float alpha,
           int heads, long sAb, long sAh, long sBb, long sBh,
           long sCb, long sCh)
{
    constexpr int BM = 128, BK = 16;
    constexpr int NPAIR = TN / 2;
    constexpr int BQ = BN / 4;
    constexpr int AS_STRIDE = 2 * BM + 8;         // 264 floats (16B-aligned rows)
    constexpr int BS_STRIDE = BN + 8;             // 16B-aligned rows
    constexpr int ASZ = BK * AS_STRIDE;
    constexpr int BSZ = BK * BS_STRIDE;
    constexpr int BIT = (BK * BQ + 255) / 256;

    extern __shared__ __align__(16) float sm[];
    // layout: [Abuf0][Abuf1][Bbuf0][Bbuf1]

    const int z = blockIdx.z;
    const int zb = z / heads, zh = z % heads;
    A  += (size_t)zb * sAb + (size_t)zh * sAh;
    Bm += (size_t)zb * sBb + (size_t)zh * sBh;
    const size_t coff = (size_t)zb * sCb + (size_t)zh * sCh;

    const int tid = threadIdx.x;
    const int tx  = tid & 15;
    const int ty  = tid >> 4;
    const int m0  = blockIdx.y * BM;
    const int n0  = blockIdx.x * BN;

    const int ar = tid >> 2;             // 0..63
    const int aq = tid & 3;              // float4 index along K

    float4 pa[2], pb[2];

    auto loadA = [&](int k0) {
        #pragma unroll
        for (int it = 0; it < 2; it++)
            pa[it] = *reinterpret_cast<const float4*>(
                &A[(size_t)(m0 + ar + it * 64) * lda + k0 + aq * 4]);
    };
    auto loadB = [&](int k0) {
        if (TRANSB) {
            #pragma unroll
            for (int it = 0; it < 2; it++)
                pb[it] = *reinterpret_cast<const float4*>(
                    &Bm[(size_t)(n0 + ar + it * 64) * ldb + k0 + aq * 4]);
        } else {
            #pragma unroll
            for (int it = 0; it < BIT; it++) {
                int idx = tid + it * 256;
                int kk = idx / BQ, nn = idx % BQ;
                pb[it] = *reinterpret_cast<const float4*>(
                    &Bm[(size_t)(k0 + kk) * ldb + n0 + nn * 4]);
            }
        }
    };
    auto storeTiles = [&](int buf) {
        float* As = sm + buf * ASZ;
        float* Bs = sm + 2 * ASZ + buf * BSZ;
        #pragma unroll
        for (int it = 0; it < 2; it++) {
            float v[4] = {pa[it].x, pa[it].y, pa[it].z, pa[it].w};
            #pragma unroll
            for (int j = 0; j < 4; j++)
                *reinterpret_cast<float2*>(
                    &As[(aq*4 + j) * AS_STRIDE + 2 * (ar + it*64)])
                    = make_float2(v[j], v[j]);
        }
        if (TRANSB) {
            #pragma unroll
            for (int it = 0; it < 2; it++) {
                float w[4] = {pb[it].x, pb[it].y, pb[it].z, pb[it].w};
                #pragma unroll
                for (int j = 0; j < 4; j++)
                    Bs[(aq*4 + j) * BS_STRIDE + ar + it*64] = w[j];
            }
        } else {
            #pragma unroll
            for (int it = 0; it < BIT; it++) {
                int idx = tid + it * 256;
                int kk = idx / BQ, nn = idx % BQ;
                *reinterpret_cast<float4*>(&Bs[kk * BS_STRIDE + nn * 4]) = pb[it];
            }
        }
    };

    ull acc[8][NPAIR];
    #pragma unroll
    for (int i = 0; i < 8; i++)
        #pragma unroll
        for (int j = 0; j < NPAIR; j++) acc[i][j] = 0ull;

    loadA(0); loadB(0);
    storeTiles(0);
    __syncthreads();
    int buf = 0;

    for (int k0 = 0; k0 < K; k0 += BK) {
        const int kn = k0 + BK;
        if (kn < K) { loadA(kn); loadB(kn); }

        const float* As = sm + buf * ASZ;
        const float* Bs = sm + 2 * ASZ + buf * BSZ;

        #pragma unroll
        for (int kk = 0; kk < BK; kk++) {
            // A broadcast pairs, pre-duplicated in shared: 4x LDS.128 = 8 pairs
            ulonglong2 a01 = *reinterpret_cast<const ulonglong2*>(
                &As[kk * AS_STRIDE + 8 * ty]);
            ulonglong2 a23 = *reinterpret_cast<const ulonglong2*>(
                &As[kk * AS_STRIDE + 8 * ty + 4]);
            ulonglong2 a45 = *reinterpret_cast<const ulonglong2*>(
                &As[kk * AS_STRIDE + 8 * ty + 128]);
            ulonglong2 a67 = *reinterpret_cast<const ulonglong2*>(
                &As[kk * AS_STRIDE + 8 * ty + 132]);
            ull aa[8] = {a01.x, a01.y, a23.x, a23.y,
                         a45.x, a45.y, a67.x, a67.y};

            ull bp[NPAIR];
            {
                ulonglong2 b0 = *reinterpret_cast<const ulonglong2*>(
                    &Bs[kk * BS_STRIDE + tx * 4]);
                bp[0] = b0.x; bp[1] = b0.y;
                if (TN == 8) {
                    ulonglong2 b1 = *reinterpret_cast<const ulonglong2*>(
                        &Bs[kk * BS_STRIDE + tx * 4 + 64]);
                    bp[2] = b1.x; bp[3] = b1.y;
                }
            }
            #pragma unroll
            for (int i = 0; i < 8; i++)
                #pragma unroll
                for (int j = 0; j < NPAIR; j++)
                    acc[i][j] = ffma2(aa[i], bp[j], acc[i][j]);
        }

        if (kn < K) {
            storeTiles(buf ^ 1);
            __syncthreads();
            buf ^= 1;
        }
    }

    // ---- epilogue
    C += coff;
    if (RESID) R += coff;
    #pragma unroll
    for (int i = 0; i < 8; i++) {
        int row = m0 + ty * 4 + (i & 3) + ((i >> 2) * 64);
        #pragma unroll
        for (int g = 0; g < TN / 4; g++) {
            size_t off = (size_t)row * ldc + n0 + tx * 4 + g * 64;
            float4 o;
            unpack2(acc[i][2*g + 0], o.x, o.y);
            unpack2(acc[i][2*g + 1], o.z, o.w);
            o.x *= alpha; o.y *= alpha; o.z *= alpha; o.w *= alpha;
            if (RESID) {
                float4 rv = *reinterpret_cast<const float4*>(&R[off]);
                o.x += rv.x; o.y += rv.y; o.z += rv.z; o.w += rv.w;
            }
            *reinterpret_cast<float4*>(&C[off]) = o;
        }
    }
}

// ---------------------------------------------------------------------------
// Row softmax over last dim (512). One block (128 thr) per row, in place.
// ---------------------------------------------------------------------------
__global__ __launch_bounds__(128)
void softmax_kernel(float* __restrict__ S)
{
    __shared__ float red[8];
    const int t = threadIdx.x;
    float* p = S + (size_t)blockIdx.x * 512;

    float x0 = p[t], x1 = p[t + 128], x2 = p[t + 256], x3 = p[t + 384];
    float m = fmaxf(fmaxf(x0, x1), fmaxf(x2, x3));
    #pragma unroll
    for (int o = 16; o; o >>= 1)
        m = fmaxf(m, __shfl_xor_sync(0xffffffffu, m, o));
    if ((t & 31) == 0) red[t >> 5] = m;
    __syncthreads();
    m = fmaxf(fmaxf(red[0], red[1]), fmaxf(red[2], red[3]));

    float e0 = exp_acc(x0 - m), e1 = exp_acc(x1 - m);
    float e2 = exp_acc(x2 - m), e3 = exp_acc(x3 - m);
    float s = (e0 + e1) + (e2 + e3);
    #pragma unroll
    for (int o = 16; o; o >>= 1)
        s += __shfl_xor_sync(0xffffffffu, s, o);
    if ((t & 31) == 0) red[4 + (t >> 5)] = s;
    __syncthreads();
    s = (red[4] + red[5]) + (red[6] + red[7]);

    float inv = 1.0f / s;
    p[t]       = e0 * inv;
    p[t + 128] = e1 * inv;
    p[t + 256] = e2 * inv;
    p[t + 384] = e3 * inv;
}

// ---------------------------------------------------------------------------
// Deterministic 2-stage BatchNorm stats.
// ---------------------------------------------------------------------------
__global__ __launch_bounds__(256)
void bn_stage1(const float* __restrict__ WX, float* __restrict__ psum,
               float* __restrict__ psq)
{
    const int blk = blockIdx.x;
    const int t   = threadIdx.x;
    const float* base = WX + (size_t)blk * 32 * HH;
    float s0 = 0.f, s1 = 0.f, q0 = 0.f, q1 = 0.f;
    for (int r = 0; r < 32; r++) {
        float a0 = base[(size_t)r * HH + t];
        float a1 = base[(size_t)r * HH + t + 256];
        s0 += a0; q0 = fmaf(a0, a0, q0);
        s1 += a1; q1 = fmaf(a1, a1, q1);
    }
    psum[(size_t)blk * HH + t]       = s0;
    psum[(size_t)blk * HH + t + 256] = s1;
    psq [(size_t)blk * HH + t]       = q0;
    psq [(size_t)blk * HH + t + 256] = q1;
}

__global__ __launch_bounds__(512)
void bn_stage2(const float* __restrict__ psum, const float* __restrict__ psq,
               float* __restrict__ sum, float* __restrict__ sq)
{
    const int h = threadIdx.x;
    float s = 0.f, q = 0.f;
    for (int i = 0; i < 256; i++) {
        s += psum[(size_t)i * HH + h];
        q += psq [(size_t)i * HH + h];
    }
    sum[h] = s;
    sq[h]  = q;
}

// ---------------------------------------------------------------------------
// Fused BN + LIF scan.
// ---------------------------------------------------------------------------
__global__ __launch_bounds__(256)
void lif_kernel(const float* __restrict__ WX,
                const float* __restrict__ sum, const float* __restrict__ sq,
                const float* __restrict__ gamma, const float* __restrict__ beta,
                float* __restrict__ out)
{
    const int g = blockIdx.x * blockDim.x + threadIdx.x;
    const int b = g >> 9;
    const int h = g & 511;

    const float inv_n = 1.0f / (float)BT;
    float mu  = sum[h] * inv_n;
    float var = fmaf(-mu, mu, sq[h] * inv_n);
    float scale = gamma[h] * __frsqrt_rn(var + 1e-5f);
    float shift = fmaf(-mu, scale, beta[h]);

    const float* wp = WX  + (size_t)b * TT * HH + h;
    float*       op = out + (size_t)b * TT * HH + h;

    float u = 0.0f;
    for (int t = 0; t < TT; t += 8) {
        float w[8];
        #pragma unroll
        for (int j = 0; j < 8; j++)
            w[j] = wp[(size_t)(t + j) * HH];
        #pragma unroll
        for (int j = 0; j < 8; j++) {
            u = fmaf(0.5f, u, fmaf(w[j], scale, shift));
            float s = (u > 1.0f) ? 1.0f : 0.0f;
            op[(size_t)(t + j) * HH] = s;
            u = (1.0f - s) * u;
        }
    }
}

// ---------------------------------------------------------------------------
// Launch
// ---------------------------------------------------------------------------
extern "C" void kernel_launch(void* const* d_in, const int* in_sizes, int n_in,
                              void* d_out, int out_size)
{
    const float* v     = (const float*)d_in[0];
    const float* a     = (const float*)d_in[1];
    const float* Wq    = (const float*)d_in[2];
    const float* Wk    = (const float*)d_in[3];
    const float* Wv    = (const float*)d_in[4];
    const float* Wo    = (const float*)d_in[5];
    const float* W     = (const float*)d_in[6];
    const float* gamma = (const float*)d_in[7];
    const float* beta  = (const float*)d_in[8];
    float* out = (float*)d_out;

    float *Q, *K, *V, *O, *X, *WX, *S, *PS, *PQ, *SM, *SQ;
    cudaGetSymbolAddress((void**)&Q,  g_Q);
    cudaGetSymbolAddress((void**)&K,  g_K);
    cudaGetSymbolAddress((void**)&V,  g_V);
    cudaGetSymbolAddress((void**)&O,  g_O);
    cudaGetSymbolAddress((void**)&X,  g_X);
    cudaGetSymbolAddress((void**)&WX, g_WX);
    cudaGetSymbolAddress((void**)&S,  g_S);
    cudaGetSymbolAddress((void**)&PS, g_psum);
    cudaGetSymbolAddress((void**)&PQ, g_psq);
    cudaGetSymbolAddress((void**)&SM, g_sum);
    cudaGetSymbolAddress((void**)&SQ, g_sq);

    const long TH = (long)TT * HH;     // 262144
    const long T2 = (long)TT * TT;     // 262144

    // Dynamic smem sizes: 2 A-bufs (dup, 264*16 fl) + 2 B-bufs ((BN+8)*16 fl)
    const int SMEM128 = (2 * 16 * 264 + 2 * 16 * 136) * 4;   // 51,200 B
    const int SMEM64  = (2 * 16 * 264 + 2 * 16 * 72)  * 4;   // 43,008 B

    static bool attr_done = false;
    if (!attr_done) {
        cudaFuncSetAttribute(gemm3<128,8,false,false>,
            cudaFuncAttributeMaxDynamicSharedMemorySize, SMEM128);
        cudaFuncSetAttribute(gemm3<128,8,true,false>,
            cudaFuncAttributeMaxDynamicSharedMemorySize, SMEM128);
        cudaFuncSetAttribute(gemm3<128,8,false,true>,
            cudaFuncAttributeMaxDynamicSharedMemorySize, SMEM128);
        cudaFuncSetAttribute(gemm3<64,4,false,false>,
            cudaFuncAttributeMaxDynamicSharedMemorySize, SMEM64);
        attr_done = true;
    }

    // 1-3) Projections: Q = v@Wq, K = a@Wk, V = a@Wv
    gemm3<128,8,false,false><<<dim3(4,64,1), 256, SMEM128>>>(v, Wq, Q, nullptr,
        BT, HH, HH, HH, HH, HH, 1.0f, 1, 0,0,0,0,0,0);
    gemm3<128,8,false,false><<<dim3(4,64,1), 256, SMEM128>>>(a, Wk, K, nullptr,
        BT, HH, HH, HH, HH, HH, 1.0f, 1, 0,0,0,0,0,0);
    gemm3<128,8,false,false><<<dim3(4,64,1), 256, SMEM128>>>(a, Wv, V, nullptr,
        BT, HH, HH, HH, HH, HH, 1.0f, 1, 0,0,0,0,0,0);

    // 4) Scores S[bh] = (1/8) * Q_h @ K_h^T
    gemm3<128,8,true,false><<<dim3(4,4,NBH), 256, SMEM128>>>(Q, K, S, nullptr,
        TT, TT, DH, HH, HH, TT, 0.125f,
        NH, TH, DH, TH, DH, (long)NH*T2, T2);

    // 5) Row softmax (in place)
    softmax_kernel<<<NBH*TT, 128>>>(S);

    // 6) O[bh] = P @ V_h
    gemm3<64,4,false,false><<<dim3(1,4,NBH), 256, SMEM64>>>(S, V, O, nullptr,
        TT, DH, TT, TT, HH, HH, 1.0f,
        NH, (long)NH*T2, T2, TH, DH, TH, DH);

    // 7) X = O @ Wo + a
    gemm3<128,8,false,true><<<dim3(4,64,1), 256, SMEM128>>>(O, Wo, X, a,
        BT, HH, HH, HH, HH, HH, 1.0f, 1, 0,0,0,0,0,0);

    // 8) WX = X @ W
    gemm3<128,8,false,false><<<dim3(4,64,1), 256, SMEM128>>>(X, W, WX, nullptr,
        BT, HH, HH, HH, HH, HH, 1.0f, 1, 0,0,0,0,0,0);

    // 9-10) Deterministic BN stats
    bn_stage1<<<256, 256>>>(WX, PS, PQ);
    bn_stage2<<<1, 512>>>(PS, PQ, SM, SQ);

    // 11) Fused BN + LIF scan -> spikes
    lif_kernel<<<32, 256>>>(WX, SM, SQ, gamma, beta, out);
}

// round 4
// speedup vs baseline: 1.3069x; 1.3069x over previous
#include <cuda_runtime.h>
#include <cstdint>

// Problem dims (fixed by the reference)
#define BB   16
#define TT   512
#define HH   512
#define BT   (BB*TT)        // 8192
#define NH   8
#define DH   64             // head dim
#define NBH  (BB*NH)        // 128 batched attention mats

typedef unsigned long long ull;

// ---------------------------------------------------------------------------
// Scratch (static device globals — no allocation)
// ---------------------------------------------------------------------------
__device__ float g_Q [(size_t)BT*HH];
__device__ float g_K [(size_t)BT*HH];
__device__ float g_V [(size_t)BT*HH];
__device__ float g_O [(size_t)BT*HH];
__device__ float g_X [(size_t)BT*HH];
__device__ float g_WX[(size_t)BT*HH];
__device__ float g_S [(size_t)NBH*TT*TT];     // 134 MB attention scores
__device__ float g_psum[(size_t)256*HH];
__device__ float g_psq [(size_t)256*HH];
__device__ float g_sum [HH];
__device__ float g_sq  [HH];

// ---------------------------------------------------------------------------
// f32x2 packed math (sm_103a FFMA2 — PTX-only)
// ---------------------------------------------------------------------------
__device__ __forceinline__ ull pack2(float x, float y) {
    ull r; asm("mov.b64 %0, {%1, %2};" : "=l"(r) : "f"(x), "f"(y)); return r;
}
__device__ __forceinline__ ull ffma2(ull a, ull b, ull c) {
    ull d; asm("fma.rn.f32x2 %0, %1, %2, %3;" : "=l"(d) : "l"(a), "l"(b), "l"(c));
    return d;
}
__device__ __forceinline__ void unpack2(ull v, float& x, float& y) {
    asm("mov.b64 {%0, %1}, %2;" : "=f"(x), "=f"(y) : "l"(v));
}

// ---------------------------------------------------------------------------
// Accurate expf, immune to --use_fast_math.
// ---------------------------------------------------------------------------
__device__ __forceinline__ float exp_acc(float x) {
    x = fmaxf(x, -87.0f);
    float z = x * 1.44269504088896341f;
    float n = rintf(z);
    float f = fmaf(n, -0.693145751953125f, x);
    f = fmaf(n, -1.428606765330187e-06f, f);
    float p = 1.9841269841e-4f;
    p = fmaf(p, f, 1.3888888889e-3f);
    p = fmaf(p, f, 8.3333333333e-3f);
    p = fmaf(p, f, 4.1666666667e-2f);
    p = fmaf(p, f, 1.6666666667e-1f);
    p = fmaf(p, f, 0.5f);
    p = fmaf(p, f, 1.0f);
    p = fmaf(p, f, 1.0f);
    int ni = (int)n;
    float sc = __int_as_float((ni + 127) << 23);
    return p * sc;
}

// ---------------------------------------------------------------------------
// fp32 GEMM, f32x2 accumulation. Round-2 inner layout (min smem traffic:
// 4x LDS.128 + pack MOVs on the idle ALU pipe) + double-buffered smem
// (single barrier per K-tile, prefetch overlap).
//   BM=128, BK=16, 256 threads, TM=8, TN(8|4).
// ---------------------------------------------------------------------------
template<int BN, int TN, bool TRANSB, bool RESID>
__global__ __launch_bounds__(256, 2)
void gemm4(const float* __restrict__ A, const float* __restrict__ Bm,
           float* __restrict__ C, const float* __restrict__ R,
           int M, int N, int K, int lda, int ldb, int ldc, float alpha,
           int heads, long sAb, long sAh, long sBb, long sBh,
           long sCb, long sCh)
{
    constexpr int BM = 128, BK = 16;
    constexpr int NPAIR = TN / 2;
    constexpr int BQ = BN / 4;
    constexpr int AS_ST = BM + 4;                 // 132
    constexpr int BS_ST = BN + 4;
    constexpr int ASZ = BK * AS_ST;
    constexpr int BSZ = BK * BS_ST;
    constexpr int BIT = (BK * BQ + 255) / 256;

    extern __shared__ __align__(16) float sm[];  // [A0][A1][B0][B1]

    const int z = blockIdx.z;
    const int zb = z / heads, zh = z % heads;
    A  += (size_t)zb * sAb + (size_t)zh * sAh;
    Bm += (size_t)zb * sBb + (size_t)zh * sBh;
    const size_t coff = (size_t)zb * sCb + (size_t)zh * sCh;

    const int tid = threadIdx.x;
    const int tx  = tid & 15;
    const int ty  = tid >> 4;
    const int m0  = blockIdx.y * BM;
    const int n0  = blockIdx.x * BN;

    const int ar = tid >> 2;             // 0..63
    const int aq = tid & 3;              // float4 index along K

    float4 pa[2], pb[2];

    auto loadA = [&](int k0) {
        #pragma unroll
        for (int it = 0; it < 2; it++)
            pa[it] = *reinterpret_cast<const float4*>(
                &A[(size_t)(m0 + ar + it * 64) * lda + k0 + aq * 4]);
    };
    auto loadB = [&](int k0) {
        if (TRANSB) {
            #pragma unroll
            for (int it = 0; it < 2; it++)
                pb[it] = *reinterpret_cast<const float4*>(
                    &Bm[(size_t)(n0 + ar + it * 64) * ldb + k0 + aq * 4]);
        } else {
            #pragma unroll
            for (int it = 0; it < BIT; it++) {
                int idx = tid + it * 256;
                int kk = idx / BQ, nn = idx % BQ;
                pb[it] = *reinterpret_cast<const float4*>(
                    &Bm[(size_t)(k0 + kk) * ldb + n0 + nn * 4]);
            }
        }
    };
    auto storeTiles = [&](int buf) {
        float* As = sm + buf * ASZ;
        float* Bs = sm + 2 * ASZ + buf * BSZ;
        #pragma unroll
        for (int it = 0; it < 2; it++) {
            As[(aq*4 + 0) * AS_ST + ar + it*64] = pa[it].x;
            As[(aq*4 + 1) * AS_ST + ar + it*64] = pa[it].y;
            As[(aq*4 + 2) * AS_ST + ar + it*64] = pa[it].z;
            As[(aq*4 + 3) * AS_ST + ar + it*64] = pa[it].w;
        }
        if (TRANSB) {
            #pragma unroll
            for (int it = 0; it < 2; it++) {
                Bs[(aq*4 + 0) * BS_ST + ar + it*64] = pb[it].x;
                Bs[(aq*4 + 1) * BS_ST + ar + it*64] = pb[it].y;
                Bs[(aq*4 + 2) * BS_ST + ar + it*64] = pb[it].z;
                Bs[(aq*4 + 3) * BS_ST + ar + it*64] = pb[it].w;
            }
        } else {
            #pragma unroll
            for (int it = 0; it < BIT; it++) {
                int idx = tid + it * 256;
                int kk = idx / BQ, nn = idx % BQ;
                *reinterpret_cast<float4*>(&Bs[kk * BS_ST + nn * 4]) = pb[it];
            }
        }
    };

    ull acc[8][NPAIR];
    #pragma unroll
    for (int i = 0; i < 8; i++)
        #pragma unroll
        for (int j = 0; j < NPAIR; j++) acc[i][j] = 0ull;

    loadA(0); loadB(0);
    storeTiles(0);
    __syncthreads();
    int buf = 0;

    for (int k0 = 0; k0 < K; k0 += BK) {
        const int kn = k0 + BK;
        if (kn < K) { loadA(kn); loadB(kn); }

        const float* As = sm + buf * ASZ;
        const float* Bs = sm + 2 * ASZ + buf * BSZ;

        #pragma unroll
        for (int kk = 0; kk < BK; kk++) {
            float4 av0 = *reinterpret_cast<const float4*>(&As[kk * AS_ST + ty * 4]);
            float4 av1 = *reinterpret_cast<const float4*>(&As[kk * AS_ST + ty * 4 + 64]);
            float a8[8] = {av0.x, av0.y, av0.z, av0.w,
                           av1.x, av1.y, av1.z, av1.w};
            ull aa[8];
            #pragma unroll
            for (int i = 0; i < 8; i++) aa[i] = pack2(a8[i], a8[i]);

            ull bp[NPAIR];
            {
                ulonglong2 b0 = *reinterpret_cast<const ulonglong2*>(&Bs[kk * BS_ST + tx * 4]);
                bp[0] = b0.x; bp[1] = b0.y;
                if (TN == 8) {
                    ulonglong2 b1 = *reinterpret_cast<const ulonglong2*>(&Bs[kk * BS_ST + tx * 4 + 64]);
                    bp[2] = b1.x; bp[3] = b1.y;
                }
            }
            #pragma unroll
            for (int i = 0; i < 8; i++)
                #pragma unroll
                for (int j = 0; j < NPAIR; j++)
                    acc[i][j] = ffma2(aa[i], bp[j], acc[i][j]);
        }

        if (kn < K) {
            storeTiles(buf ^ 1);
            __syncthreads();
            buf ^= 1;
        }
    }

    // ---- epilogue
    C += coff;
    if (RESID) R += coff;
    #pragma unroll
    for (int i = 0; i < 8; i++) {
        int row = m0 + ty * 4 + (i & 3) + ((i >> 2) * 64);
        #pragma unroll
        for (int g = 0; g < TN / 4; g++) {
            size_t off = (size_t)row * ldc + n0 + tx * 4 + g * 64;
            float4 o;
            unpack2(acc[i][2*g + 0], o.x, o.y);
            unpack2(acc[i][2*g + 1], o.z, o.w);
            o.x *= alpha; o.y *= alpha; o.z *= alpha; o.w *= alpha;
            if (RESID) {
                float4 rv = *reinterpret_cast<const float4*>(&R[off]);
                o.x += rv.x; o.y += rv.y; o.z += rv.z; o.w += rv.w;
            }
            *reinterpret_cast<float4*>(&C[off]) = o;
        }
    }
}

// ---------------------------------------------------------------------------
// Row softmax over last dim (512). One block (128 thr) per row, in place.
// ---------------------------------------------------------------------------
__global__ __launch_bounds__(128)
void softmax_kernel(float* __restrict__ S)
{
    __shared__ float red[8];
    const int t = threadIdx.x;
    float* p = S + (size_t)blockIdx.x * 512;

    float x0 = p[t], x1 = p[t + 128], x2 = p[t + 256], x3 = p[t + 384];
    float m = fmaxf(fmaxf(x0, x1), fmaxf(x2, x3));
    #pragma unroll
    for (int o = 16; o; o >>= 1)
        m = fmaxf(m, __shfl_xor_sync(0xffffffffu, m, o));
    if ((t & 31) == 0) red[t >> 5] = m;
    __syncthreads();
    m = fmaxf(fmaxf(red[0], red[1]), fmaxf(red[2], red[3]));

    float e0 = exp_acc(x0 - m), e1 = exp_acc(x1 - m);
    float e2 = exp_acc(x2 - m), e3 = exp_acc(x3 - m);
    float s = (e0 + e1) + (e2 + e3);
    #pragma unroll
    for (int o = 16; o; o >>= 1)
        s += __shfl_xor_sync(0xffffffffu, s, o);
    if ((t & 31) == 0) red[4 + (t >> 5)] = s;
    __syncthreads();
    s = (red[4] + red[5]) + (red[6] + red[7]);

    float inv = 1.0f / s;
    p[t]       = e0 * inv;
    p[t + 128] = e1 * inv;
    p[t + 256] = e2 * inv;
    p[t + 384] = e3 * inv;
}

// ---------------------------------------------------------------------------
// Deterministic 2-stage BatchNorm stats.
// ---------------------------------------------------------------------------
__global__ __launch_bounds__(256)
void bn_stage1(const float* __restrict__ WX, float* __restrict__ psum,
               float* __restrict__ psq)
{
    const int blk = blockIdx.x;
    const int t   = threadIdx.x;
    const float* base = WX + (size_t)blk * 32 * HH;
    float s0 = 0.f, s1 = 0.f, q0 = 0.f, q1 = 0.f;
    for (int r = 0; r < 32; r++) {
        float a0 = base[(size_t)r * HH + t];
        float a1 = base[(size_t)r * HH + t + 256];
        s0 += a0; q0 = fmaf(a0, a0, q0);
        s1 += a1; q1 = fmaf(a1, a1, q1);
    }
    psum[(size_t)blk * HH + t]       = s0;
    psum[(size_t)blk * HH + t + 256] = s1;
    psq [(size_t)blk * HH + t]       = q0;
    psq [(size_t)blk * HH + t + 256] = q1;
}

__global__ __launch_bounds__(512)
void bn_stage2(const float* __restrict__ psum, const float* __restrict__ psq,
               float* __restrict__ sum, float* __restrict__ sq)
{
    const int h = threadIdx.x;
    float s = 0.f, q = 0.f;
    for (int i = 0; i < 256; i++) {
        s += psum[(size_t)i * HH + h];
        q += psq [(size_t)i * HH + h];
    }
    sum[h] = s;
    sq[h]  = q;
}

// ---------------------------------------------------------------------------
// Fused BN + LIF scan.
// ---------------------------------------------------------------------------
__global__ __launch_bounds__(256)
void lif_kernel(const float* __restrict__ WX,
                const float* __restrict__ sum, const float* __restrict__ sq,
                const float* __restrict__ gamma, const float* __restrict__ beta,
                float* __restrict__ out)
{
    const int g = blockIdx.x * blockDim.x + threadIdx.x;
    const int b = g >> 9;
    const int h = g & 511;

    const float inv_n = 1.0f / (float)BT;
    float mu  = sum[h] * inv_n;
    float var = fmaf(-mu, mu, sq[h] * inv_n);
    float scale = gamma[h] * __frsqrt_rn(var + 1e-5f);
    float shift = fmaf(-mu, scale, beta[h]);

    const float* wp = WX  + (size_t)b * TT * HH + h;
    float*       op = out + (size_t)b * TT * HH + h;

    float u = 0.0f;
    for (int t = 0; t < TT; t += 8) {
        float w[8];
        #pragma unroll
        for (int j = 0; j < 8; j++)
            w[j] = wp[(size_t)(t + j) * HH];
        #pragma unroll
        for (int j = 0; j < 8; j++) {
            u = fmaf(0.5f, u, fmaf(w[j], scale, shift));
            float s = (u > 1.0f) ? 1.0f : 0.0f;
            op[(size_t)(t + j) * HH] = s;
            u = (1.0f - s) * u;
        }
    }
}

// ---------------------------------------------------------------------------
// Launch
// ---------------------------------------------------------------------------
extern "C" void kernel_launch(void* const* d_in, const int* in_sizes, int n_in,
                              void* d_out, int out_size)
{
    const float* v     = (const float*)d_in[0];
    const float* a     = (const float*)d_in[1];
    const float* Wq    = (const float*)d_in[2];
    const float* Wk    = (const float*)d_in[3];
    const float* Wv    = (const float*)d_in[4];
    const float* Wo    = (const float*)d_in[5];
    const float* W     = (const float*)d_in[6];
    const float* gamma = (const float*)d_in[7];
    const float* beta  = (const float*)d_in[8];
    float* out = (float*)d_out;

    float *Q, *K, *V, *O, *X, *WX, *S, *PS, *PQ, *SM, *SQ;
    cudaGetSymbolAddress((void**)&Q,  g_Q);
    cudaGetSymbolAddress((void**)&K,  g_K);
    cudaGetSymbolAddress((void**)&V,  g_V);
    cudaGetSymbolAddress((void**)&O,  g_O);
    cudaGetSymbolAddress((void**)&X,  g_X);
    cudaGetSymbolAddress((void**)&WX, g_WX);
    cudaGetSymbolAddress((void**)&S,  g_S);
    cudaGetSymbolAddress((void**)&PS, g_psum);
    cudaGetSymbolAddress((void**)&PQ, g_psq);
    cudaGetSymbolAddress((void**)&SM, g_sum);
    cudaGetSymbolAddress((void**)&SQ, g_sq);

    const long TH = (long)TT * HH;     // 262144
    const long T2 = (long)TT * TT;     // 262144

    // Dynamic smem: 2 A-bufs (16x132) + 2 B-bufs (16x(BN+4)) floats
    const int SMEM128 = (2 * 16 * 132 + 2 * 16 * 132) * 4;   // 33,792 B
    const int SMEM64  = (2 * 16 * 132 + 2 * 16 * 68)  * 4;   // 25,600 B

    // 1-3) Projections: Q = v@Wq, K = a@Wk, V = a@Wv
    gemm4<128,8,false,false><<<dim3(4,64,1), 256, SMEM128>>>(v, Wq, Q, nullptr,
        BT, HH, HH, HH, HH, HH, 1.0f, 1, 0,0,0,0,0,0);
    gemm4<128,8,false,false><<<dim3(4,64,1), 256, SMEM128>>>(a, Wk, K, nullptr,
        BT, HH, HH, HH, HH, HH, 1.0f, 1, 0,0,0,0,0,0);
    gemm4<128,8,false,false><<<dim3(4,64,1), 256, SMEM128>>>(a, Wv, V, nullptr,
        BT, HH, HH, HH, HH, HH, 1.0f, 1, 0,0,0,0,0,0);

    // 4) Scores S[bh] = (1/8) * Q_h @ K_h^T
    gemm4<128,8,true,false><<<dim3(4,4,NBH), 256, SMEM128>>>(Q, K, S, nullptr,
        TT, TT, DH, HH, HH, TT, 0.125f,
        NH, TH, DH, TH, DH, (long)NH*T2, T2);

    // 5) Row softmax (in place)
    softmax_kernel<<<NBH*TT, 128>>>(S);

    // 6) O[bh] = P @ V_h
    gemm4<64,4,false,false><<<dim3(1,4,NBH), 256, SMEM64>>>(S, V, O, nullptr,
        TT, DH, TT, TT, HH, HH, 1.0f,
        NH, (long)NH*T2, T2, TH, DH, TH, DH);

    // 7) X = O @ Wo + a
    gemm4<128,8,false,true><<<dim3(4,64,1), 256, SMEM128>>>(O, Wo, X, a,
        BT, HH, HH, HH, HH, HH, 1.0f, 1, 0,0,0,0,0,0);

    // 8) WX = X @ W
    gemm4<128,8,false,false><<<dim3(4,64,1), 256, SMEM128>>>(X, W, WX, nullptr,
        BT, HH, HH, HH, HH, HH, 1.0f, 1, 0,0,0,0,0,0);

    // 9-10) Deterministic BN stats
    bn_stage1<<<256, 256>>>(WX, PS, PQ);
    bn_stage2<<<1, 512>>>(PS, PQ, SM, SQ);

    // 11) Fused BN + LIF scan -> spikes
    lif_kernel<<<32, 256>>>(WX, SM, SQ, gamma, beta, out);
}